// round 6
// baseline (speedup 1.0000x reference)
#include <cuda_runtime.h>
#include <cuda_bf16.h>

// Mat2Twist: rotation matrix (3x3) -> axis-angle vector (3). Memory-bound.
//
// R6: isolate the R5 regression. Same 512-matrices-per-block shape as R5
// (deep load batch, half the barriers of R1), but with PLAIN loads/stores —
// the __ldcs/__stcs streaming hints are removed (suspected cause of the
// DRAM 72%->61% drop).
// smem: 512*9*4 + 512*3*4 = 24KB -> 4 blocks/SM, full 32-warp occupancy.

#define TPB 256
#define MPB (TPB * 2)   // matrices per block = 512

__global__ __launch_bounds__(TPB) void mat2twist_kernel(
    const float* __restrict__ in, float* __restrict__ out, int n)
{
    __shared__ float s_in[MPB * 9];    // 18432 B
    __shared__ float s_out[MPB * 3];   // 6144 B

    const int tid = threadIdx.x;
    const int blockMat = blockIdx.x * MPB;

    if (blockMat + MPB <= n) {
        // ---- coalesced vectorized load: 1152 float4 per block ----
        const float4* __restrict__ gin =
            reinterpret_cast<const float4*>(in + (size_t)blockMat * 9);
        float4* s_in4 = reinterpret_cast<float4*>(s_in);

        // 1152 / 256 = 4.5 per thread; fully unrolled, all independent.
        float4 v0 = gin[tid];
        float4 v1 = gin[tid + TPB];
        float4 v2 = gin[tid + 2 * TPB];
        float4 v3 = gin[tid + 3 * TPB];
        float4 v4;
        if (tid < TPB / 2) v4 = gin[tid + 4 * TPB];
        s_in4[tid]           = v0;
        s_in4[tid + TPB]     = v1;
        s_in4[tid + 2 * TPB] = v2;
        s_in4[tid + 3 * TPB] = v3;
        if (tid < TPB / 2) s_in4[tid + 4 * TPB] = v4;
        __syncthreads();

        // ---- compute 2 matrices per thread ----
        #pragma unroll
        for (int k = 0; k < 2; k++) {
            const int mi = tid + k * TPB;
            const float* m = &s_in[mi * 9];
            float m00 = m[0], m01 = m[1], m02 = m[2];
            float m10 = m[3], m11 = m[4], m12 = m[5];
            float m20 = m[6], m21 = m[7], m22 = m[8];

            float c = 0.5f * (m00 + m11 + m22 - 1.0f);
            c = fminf(1.0f, fmaxf(-1.0f, c));
            float angle = acosf(c);
            float scale = angle / (2.0f * sinf(angle));

            s_out[mi * 3 + 0] = scale * (m21 - m12);
            s_out[mi * 3 + 1] = scale * (m02 - m20);
            s_out[mi * 3 + 2] = scale * (m10 - m01);
        }
        __syncthreads();

        // ---- coalesced vectorized store: 384 float4 per block ----
        float4* __restrict__ gout =
            reinterpret_cast<float4*>(out + (size_t)blockMat * 3);
        const float4* s_out4 = reinterpret_cast<const float4*>(s_out);
        gout[tid] = s_out4[tid];
        if (tid < TPB / 2)
            gout[tid + TPB] = s_out4[tid + TPB];
    } else {
        // ---- tail path: scalar, bounds-checked ----
        #pragma unroll
        for (int k = 0; k < 2; k++) {
            int i = blockMat + tid + k * TPB;
            if (i < n) {
                const float* m = in + (size_t)i * 9;
                float m00 = m[0], m01 = m[1], m02 = m[2];
                float m10 = m[3], m11 = m[4], m12 = m[5];
                float m20 = m[6], m21 = m[7], m22 = m[8];

                float c = 0.5f * (m00 + m11 + m22 - 1.0f);
                c = fminf(1.0f, fmaxf(-1.0f, c));
                float angle = acosf(c);
                float scale = angle / (2.0f * sinf(angle));

                out[(size_t)i * 3 + 0] = scale * (m21 - m12);
                out[(size_t)i * 3 + 1] = scale * (m02 - m20);
                out[(size_t)i * 3 + 2] = scale * (m10 - m01);
            }
        }
    }
}

extern "C" void kernel_launch(void* const* d_in, const int* in_sizes, int n_in,
                              void* d_out, int out_size)
{
    const float* in = (const float*)d_in[0];
    float* out = (float*)d_out;
    int n = in_sizes[0] / 9;           // number of matrices
    int grid = (n + MPB - 1) / MPB;
    mat2twist_kernel<<<grid, TPB>>>(in, out, n);
}

// round 7
// speedup vs baseline: 1.2339x; 1.2339x over previous
#include <cuda_runtime.h>
#include <cuda_bf16.h>

// Mat2Twist: rotation matrix (3x3) -> axis-angle vector (3). Memory-bound.
//
// R7 = R1 geometry (best measured: 256 mats / 256-thread block, DRAM 72%)
//      + __ldcs/__stcs streaming hints (measured +4% at fixed shape in R5/R6;
//        input 151MB > L2 126MB, touch-once)
//      + sin(acos(c)) = sqrt(1-c^2): scale = 0.5*acos(c)*rsqrt(1-c^2),
//        removing the sinf MUFU and its serial dependency.
// smem: 256*9*4 + 256*3*4 = 12KB.

#define TPB 256

__global__ __launch_bounds__(TPB) void mat2twist_kernel(
    const float* __restrict__ in, float* __restrict__ out, int n)
{
    __shared__ float s_in[TPB * 9];    // 9216 B
    __shared__ float s_out[TPB * 3];   // 3072 B

    const int tid = threadIdx.x;
    const int blockMat = blockIdx.x * TPB;

    if (blockMat + TPB <= n) {
        // ---- coalesced vectorized load: 576 float4 per block ----
        const float4* __restrict__ gin =
            reinterpret_cast<const float4*>(in + (size_t)blockMat * 9);
        float4* s_in4 = reinterpret_cast<float4*>(s_in);

        float4 v0 = __ldcs(gin + tid);
        float4 v1 = __ldcs(gin + tid + TPB);
        float4 v2;
        if (tid < TPB / 4) v2 = __ldcs(gin + tid + 2 * TPB);
        s_in4[tid]       = v0;
        s_in4[tid + TPB] = v1;
        if (tid < TPB / 4) s_in4[tid + 2 * TPB] = v2;
        __syncthreads();

        // ---- compute ----
        const float* m = &s_in[tid * 9];
        float m00 = m[0], m01 = m[1], m02 = m[2];
        float m10 = m[3], m11 = m[4], m12 = m[5];
        float m20 = m[6], m21 = m[7], m22 = m[8];

        float c = 0.5f * (m00 + m11 + m22 - 1.0f);
        c = fminf(1.0f, fmaxf(-1.0f, c));
        // sin(acos(c)) = sqrt(1-c^2); theta in [0.1, pi-0.1] so 1-c^2 >= ~0.01
        float scale = 0.5f * acosf(c) * rsqrtf(fmaxf(1.0f - c * c, 1e-12f));

        s_out[tid * 3 + 0] = scale * (m21 - m12);
        s_out[tid * 3 + 1] = scale * (m02 - m20);
        s_out[tid * 3 + 2] = scale * (m10 - m01);
        __syncthreads();

        // ---- coalesced vectorized store: 192 float4 per block ----
        float4* __restrict__ gout =
            reinterpret_cast<float4*>(out + (size_t)blockMat * 3);
        const float4* s_out4 = reinterpret_cast<const float4*>(s_out);
        if (tid < (TPB * 3) / 4)
            __stcs(gout + tid, s_out4[tid]);
    } else {
        // ---- tail path: scalar, bounds-checked ----
        int i = blockMat + tid;
        if (i < n) {
            const float* m = in + (size_t)i * 9;
            float m00 = m[0], m01 = m[1], m02 = m[2];
            float m10 = m[3], m11 = m[4], m12 = m[5];
            float m20 = m[6], m21 = m[7], m22 = m[8];

            float c = 0.5f * (m00 + m11 + m22 - 1.0f);
            c = fminf(1.0f, fmaxf(-1.0f, c));
            float scale = 0.5f * acosf(c) * rsqrtf(fmaxf(1.0f - c * c, 1e-12f));

            out[(size_t)i * 3 + 0] = scale * (m21 - m12);
            out[(size_t)i * 3 + 1] = scale * (m02 - m20);
            out[(size_t)i * 3 + 2] = scale * (m10 - m01);
        }
    }
}

extern "C" void kernel_launch(void* const* d_in, const int* in_sizes, int n_in,
                              void* d_out, int out_size)
{
    const float* in = (const float*)d_in[0];
    float* out = (float*)d_out;
    int n = in_sizes[0] / 9;           // number of matrices
    int grid = (n + TPB - 1) / TPB;
    mat2twist_kernel<<<grid, TPB>>>(in, out, n);
}